// round 2
// baseline (speedup 1.0000x reference)
#include <cuda_runtime.h>
#include <cuda_bf16.h>
#include <math.h>

// Spectral (eigendecomposition) evaluation of the reference power iteration.
//
// Reference computes (after telescoping the per-step normalization):
//     out = (A^T e_s)[z],  z = IDX_Z = 512, s = idx_s, T = idx_T
// where A is the 1023x1023 tridiagonal Toeplitz matrix
//     A[j,j-1]=p2, A[j,j]=pmid, A[j,j+1]=p1   (Dirichlet boundaries)
// Closed form:
//     out = (p2/p1)^{(z-s)/2} * (2/1024) *
//           sum_{k=1}^{1023} lam_k^T sin(z k pi/1024) sin(s k pi/1024)
//     lam_k = pmid + 2 sqrt(p1 p2) cos(k pi / 1024)

#define NBLK 64
#define TPB  32

__device__ double g_partials[NBLK];

struct Coef {
    double sq;     // sqrt(p1*p2)
    double d2;     // (sqrt(p1)-sqrt(p2))^2, cancellation-free
    double delta;  // (1 - pmid) - (p1 + p2)   (pmid f32 rounding residual)
    double p1d, p2d;
};

__device__ __forceinline__ Coef make_coef(float mu) {
    // Replicate the reference's float32 coefficient computation exactly.
    // DX = 2/1024 = 2^-9 (exact), DX^2 = 2^-18 (exact) -> divisions are exact scalings.
    float m1 = mu * 2e-6f;
    float m2 = m1 * m1 + 2e-6f;
    float a  = m2 * 262144.0f;   // m2 / DX^2 (exact scaling)
    float b  = m1 * 512.0f;      // m1 / DX   (exact scaling)
    float p1 = (a + b) * 0.5f;
    float p2 = (a - b) * 0.5f;
    float pmid = 1.0f - p1 - p2;

    Coef c;
    c.p1d = (double)p1;
    c.p2d = (double)p2;
    c.sq  = sqrt(c.p1d * c.p2d);
    double dif = c.p1d - c.p2d;                       // exact in double
    c.d2  = dif * dif / (c.p1d + c.p2d + 2.0 * c.sq); // = (sqrt(p1)-sqrt(p2))^2
    c.delta = (1.0 - (double)pmid) - (c.p1d + c.p2d); // exact in double
    return c;
}

__global__ void spectral_partial(const float* __restrict__ muP,
                                 const int* __restrict__ TP,
                                 const int* __restrict__ sP) {
    const int   T = TP[0];
    const int   s = sP[0];
    const int   z = 512;  // IDX_Z
    const Coef  c = make_coef(muP[0]);

    // Stride k across blocks so surviving (small-k) modes spread over all SMs.
    int k = 1 + (int)threadIdx.x * NBLK + (int)blockIdx.x;

    double term = 0.0;
    if (k <= 1023 && s >= 1 && s <= 1023) {
        // Cheap f32 screening: eps_k = 1 - lam_k (no cancellation).
        float spf  = sinpif((float)k * (1.0f / 2048.0f));
        float epsf = (float)c.d2 + 4.0f * (float)c.sq * spf * spf;
        if (!((double)T * (double)epsf > 80.0)) {
            // Exact (double) evaluation for surviving modes.
            double sp  = sinpi((double)k / 2048.0);
            double eps = c.d2 + 4.0 * c.sq * sp * sp + c.delta;  // 1 - lam_k
            double lam = 1.0 - eps;
            double al  = fabs(lam);
            if (al > 0.0) {
                double w = (double)T * log(al);
                if (w > -745.0) {
                    double val = exp(w);
                    if (lam < 0.0 && (T & 1)) val = -val;
                    // sin(j k pi / 1024) with exact integer reduction mod 2048
                    double sz = sinpi((double)((z * k) & 2047) * (1.0 / 1024.0));
                    double ss = sinpi((double)((s * k) & 2047) * (1.0 / 1024.0));
                    term = val * sz * ss;
                }
            }
        }
    }

    // Warp reduction (TPB == 32)
    #pragma unroll
    for (int o = 16; o > 0; o >>= 1)
        term += __shfl_down_sync(0xffffffffu, term, o);

    if (threadIdx.x == 0)
        g_partials[blockIdx.x] = term;
}

__global__ void spectral_finalize(const float* __restrict__ muP,
                                  const int* __restrict__ sP,
                                  float* __restrict__ out) {
    int t = threadIdx.x;  // 32 threads
    double v = g_partials[t] + g_partials[t + 32];
    #pragma unroll
    for (int o = 16; o > 0; o >>= 1)
        v += __shfl_down_sync(0xffffffffu, v, o);

    if (t == 0) {
        const int  s = sP[0];
        const int  z = 512;
        const Coef c = make_coef(muP[0]);
        // Similarity prefactor (p2/p1)^{(z-s)/2}
        double pref = exp(0.5 * (double)(z - s) * log(c.p2d / c.p1d));
        out[0] = (float)(pref * (2.0 / 1024.0) * v);
    }
}

extern "C" void kernel_launch(void* const* d_in, const int* in_sizes, int n_in,
                              void* d_out, int out_size) {
    const float* mu    = (const float*)d_in[0];
    const int*   idx_T = (const int*)d_in[1];
    const int*   idx_s = (const int*)d_in[2];
    float*       out   = (float*)d_out;

    spectral_partial<<<NBLK, TPB>>>(mu, idx_T, idx_s);
    spectral_finalize<<<1, TPB>>>(mu, idx_s, out);
}